// round 11
// baseline (speedup 1.0000x reference)
#include <cuda_runtime.h>
#include <cuda_fp16.h>
#include <cstdint>

#define NROWS 65536
#define D 128
#define TMAX 2048

// smem: rp 4KB | 3 stages x (A 16KB + W 16KB)
#define A_OFF   4096
#define STAGE   32768
#define SMEM_SZ (4096 + 3 * 32768)

// ---------------- scratch ----------------
__device__ __half g_G16[(size_t)2 * NROWS * 512];   // per row: [r_sum | z_sum | inn | hn]
__device__ __half g_mem16[2][(size_t)NROWS * D];
__device__ __half g_feat16[2][(size_t)NROWS * D];
__device__ __half g_TEtab16[2 * TMAX * D];
__device__ __half g_Wih16[2][384 * 512];
__device__ __half g_Whh16[2][384 * 128];
__device__ int g_hidx[NROWS], g_gidx[NROWS], g_trel[NROWS], g_fidx1[NROWS], g_pick[NROWS];

// ---------------- ptx helpers ----------------
__device__ __forceinline__ void mma_f16(float* c, const uint32_t* a, uint32_t b0, uint32_t b1) {
    asm volatile(
        "mma.sync.aligned.m16n8k16.row.col.f32.f16.f16.f32 "
        "{%0,%1,%2,%3}, {%4,%5,%6,%7}, {%8,%9}, {%0,%1,%2,%3};\n"
        : "+f"(c[0]), "+f"(c[1]), "+f"(c[2]), "+f"(c[3])
        : "r"(a[0]), "r"(a[1]), "r"(a[2]), "r"(a[3]), "r"(b0), "r"(b1));
}
__device__ __forceinline__ void cp16(uint32_t dst, const void* src) {
    asm volatile("cp.async.cg.shared.global [%0], [%1], 16;\n" :: "r"(dst), "l"(src));
}
__device__ __forceinline__ void ldsm4(uint32_t* r, uint32_t addr) {
    asm volatile("ldmatrix.sync.aligned.m8n8.x4.shared.b16 {%0,%1,%2,%3}, [%4];"
                 : "=r"(r[0]), "=r"(r[1]), "=r"(r[2]), "=r"(r[3]) : "r"(addr));
}

// ---------------- one-time conversion kernels ----------------
__global__ void te_table16_kernel(const float* __restrict__ wm, const float* __restrict__ bm,
                                  const float* __restrict__ wp, const float* __restrict__ bp)
{
    int t = blockIdx.x, k = threadIdx.x;
    float tf = (float)t;
    g_TEtab16[t * D + k]            = __float2half_rn(cosf(tf * wm[k] + bm[k]));
    g_TEtab16[TMAX * D + t * D + k] = __float2half_rn(cosf(tf * wp[k] + bp[k]));
}

__global__ void wround16_kernel(const float* __restrict__ Wih0, const float* __restrict__ Wih1,
                                const float* __restrict__ Whh0, const float* __restrict__ Whh1)
{
    int which = blockIdx.y;
    int n = (which < 2) ? 384 * 512 : 384 * 128;
    int i = blockIdx.x * 256 + threadIdx.x;
    if (i >= n) return;
    const float* s = (which == 0) ? Wih0 : (which == 1) ? Wih1 : (which == 2) ? Whh0 : Whh1;
    __half* d      = (which == 0) ? g_Wih16[0] : (which == 1) ? g_Wih16[1]
                   : (which == 2) ? g_Whh16[0] : g_Whh16[1];
    d[i] = __float2half_rn(s[i]);
}

__global__ void conv_mem_kernel(const float* __restrict__ m0, const float* __restrict__ m1)
{
    int arr = blockIdx.y;
    const float* s = arr ? m1 : m0;
    __half* d = g_mem16[arr];
    size_t i = ((size_t)blockIdx.x * 256 + threadIdx.x) * 4;
    float4 v = *(const float4*)(s + i);
    *(__half2*)(d + i)     = __floats2half2_rn(v.x, v.y);
    *(__half2*)(d + i + 2) = __floats2half2_rn(v.z, v.w);
}

// ---------------- descriptors + last_up ----------------
__global__ void prep_kernel(const int* __restrict__ n_id,
                            const int* __restrict__ other_s, const int* __restrict__ other_d,
                            const int* __restrict__ t_s, const int* __restrict__ t_d,
                            const int* __restrict__ last_update,
                            float* __restrict__ out)
{
    int row = blockIdx.x * 256 + threadIdx.x;
    if (row >= NROWS) return;
    int ts = t_s[row], td = t_d[row];
    bool pick = (ts >= td);
    int nid = n_id[row];
    int tpick = pick ? ts : td;
    g_hidx[row]  = nid;
    g_gidx[row]  = pick ? other_s[row] : other_d[row];
    g_trel[row]  = tpick - last_update[nid];
    g_pick[row]  = pick ? 1 : 0;
    g_fidx1[row] = pick ? nid : other_d[row];
    out[(size_t)2 * NROWS * D + row] = (float)tpick;
}

// ---------------- feature pick/gather + convert ----------------
__global__ void feat_kernel(const float* __restrict__ msg_s, const float* __restrict__ msg_d,
                            const float* __restrict__ pos_emb)
{
    int warp = threadIdx.x >> 5, lane = threadIdx.x & 31;
    int row = blockIdx.x * 4 + (warp >> 1);
    int br  = warp & 1;
    const float* src = br ? pos_emb + (size_t)g_fidx1[row] * D
                          : (g_pick[row] ? msg_s : msg_d) + (size_t)row * D;
    float4 v = *(const float4*)(src + lane * 4);
    __half* d = g_feat16[br] + (size_t)row * D + lane * 4;
    *(__half2*)d       = __floats2half2_rn(v.x, v.y);
    *(__half2*)(d + 2) = __floats2half2_rn(v.z, v.w);
}

// ---------------- pipelined FP16 GEMM, 128 threads, 4 warps m64n64, BK=64 ----------------
// grid (512 row-blocks, 4 gate-blocks, 2 branches); BM=128, BN=128.
// gates: nb0=r_sum (10 slabs: 8 Wih + 2 Whh), nb1=z_sum (10), nb2=inn (8), nb3=hn (2)
__global__ void __launch_bounds__(128)
gemm16_kernel()
{
    extern __shared__ char sm[];
    const __half** rp = (const __half**)sm;
    uint32_t su = (uint32_t)__cvta_generic_to_shared(sm);

    int br = blockIdx.z, nb = blockIdx.y, rb = blockIdx.x;
    int NSslab = (nb == 3) ? 2 : ((nb == 2) ? 8 : 10);
    int whh_base = (nb < 2) ? nb * 128 : 256;

    const __half* WihB = g_Wih16[br];
    const __half* WhhB = g_Whh16[br];

    int tid = threadIdx.x, lane = tid & 31, warp = tid >> 5;
    int wm = warp & 1, wn = warp >> 1;

    {
        int R = rb * 128 + tid;
        rp[tid]       = g_mem16[br] + (size_t)g_hidx[R] * D;
        rp[128 + tid] = g_mem16[br] + (size_t)g_gidx[R] * D;
        rp[256 + tid] = g_feat16[br] + (size_t)R * D;
        rp[384 + tid] = g_TEtab16 + (size_t)br * TMAX * D + (size_t)g_trel[R] * D;
    }
    __syncthreads();

    int arow = tid;           // loader: thread covers A row tid and W row tid, 8 granules each
    int ax7  = arow & 7;

    auto issue = [&](int s) {
        if (s < NSslab) {
            uint32_t base = su + A_OFF + (s % 3) * STAGE;
            bool is_wih = (nb <= 2) && (s < 8);
            int c     = is_wih ? (s >> 1) : 0;
            int koffA = is_wih ? (s & 1) * 128 : ((nb < 2) ? (s - 8) : s) * 128;  // bytes
            const char* ap = (const char*)rp[c * 128 + arow] + koffA;
            const char* wp;
            if (is_wih) wp = (const char*)(WihB + (size_t)(nb * 128 + arow) * 512) + s * 128;
            else        wp = (const char*)(WhhB + (size_t)(whh_base + arow) * 128) + koffA;
            uint32_t ad = base + arow * 128;
            uint32_t wd = base + 16384 + arow * 128;
            #pragma unroll
            for (int j = 0; j < 8; ++j) {
                uint32_t sw = (uint32_t)((j ^ ax7) << 4);
                cp16(ad + sw, ap + j * 16);
                cp16(wd + sw, wp + j * 16);
            }
        }
        asm volatile("cp.async.commit_group;\n");
    };

    // fragment lane constants
    int x7 = lane & 7;
    int a_kh = lane >> 4;
    int b_kh = (lane >> 3) & 1;
    uint32_t aRowOff = (uint32_t)((wm * 64 + ((lane >> 3) & 1) * 8 + (lane & 7)) * 128);
    uint32_t bRowOff = (uint32_t)((wn * 64 + (lane >> 4) * 8 + (lane & 7)) * 128);

    float acc[4][8][4];
    #pragma unroll
    for (int i = 0; i < 4; ++i)
        #pragma unroll
        for (int n = 0; n < 8; ++n)
            #pragma unroll
            for (int q = 0; q < 4; ++q) acc[i][n][q] = 0.f;

    issue(0);
    issue(1);

    for (int s = 0; s < NSslab; ++s) {
        asm volatile("cp.async.wait_group 1;\n");
        __syncthreads();
        issue(s + 2);

        uint32_t aSt = su + A_OFF + (s % 3) * STAGE;
        uint32_t wSt = aSt + 16384;
        #pragma unroll
        for (int s2 = 0; s2 < 4; ++s2) {
            uint32_t aj = (uint32_t)(((s2 * 2 + a_kh) ^ x7) << 4);
            uint32_t bj = (uint32_t)(((s2 * 2 + b_kh) ^ x7) << 4);
            uint32_t Af[4][4];
            #pragma unroll
            for (int mf = 0; mf < 4; ++mf)
                ldsm4(Af[mf], aSt + aRowOff + mf * 2048 + aj);
            uint32_t Bf[4][4];
            #pragma unroll
            for (int p = 0; p < 4; ++p)
                ldsm4(Bf[p], wSt + bRowOff + p * 2048 + bj);
            #pragma unroll
            for (int nf = 0; nf < 8; ++nf) {
                uint32_t b0 = Bf[nf >> 1][(nf & 1) * 2];
                uint32_t b1 = Bf[nf >> 1][(nf & 1) * 2 + 1];
                #pragma unroll
                for (int mf = 0; mf < 4; ++mf)
                    mma_f16(&acc[mf][nf][0], Af[mf], b0, b1);
            }
        }
    }

    // store to G16
    size_t gb = (size_t)br * NROWS * 512;
    #pragma unroll
    for (int mf = 0; mf < 4; ++mf) {
        int r = rb * 128 + wm * 64 + mf * 16 + (lane >> 2);
        #pragma unroll
        for (int nf = 0; nf < 8; ++nf) {
            int col = nb * 128 + wn * 64 + nf * 8 + (lane & 3) * 2;
            *(__half2*)&g_G16[gb + (size_t)r * 512 + col]       = __floats2half2_rn(acc[mf][nf][0], acc[mf][nf][1]);
            *(__half2*)&g_G16[gb + (size_t)(r + 8) * 512 + col] = __floats2half2_rn(acc[mf][nf][2], acc[mf][nf][3]);
        }
    }
}

// ---------------- GRU epilogue: warp per row ----------------
__global__ void gru_kernel(const float* __restrict__ memory, const float* __restrict__ pos_mem,
                           const float* __restrict__ bih0, const float* __restrict__ bhh0,
                           const float* __restrict__ bih1, const float* __restrict__ bhh1,
                           float* __restrict__ out)
{
    int warp = threadIdx.x >> 5, lane = threadIdx.x & 31;
    int row = blockIdx.x * 8 + warp;
    int br  = blockIdx.y;
    int j   = lane * 4;
    const __half* G  = g_G16 + ((size_t)br * NROWS + row) * 512;
    const float* bih = br ? bih1 : bih0;
    const float* bhh = br ? bhh1 : bhh0;
    const float* mem = br ? pos_mem : memory;

    uint2 grv = *(const uint2*)&G[j];
    uint2 gzv = *(const uint2*)&G[128 + j];
    uint2 giv = *(const uint2*)&G[256 + j];
    uint2 ghv = *(const uint2*)&G[384 + j];
    float gr[4], gz[4], gi[4], gh[4];
    {
        float2 a = __half22float2(*(__half2*)&grv.x), b = __half22float2(*(__half2*)&grv.y);
        gr[0] = a.x; gr[1] = a.y; gr[2] = b.x; gr[3] = b.y;
        a = __half22float2(*(__half2*)&gzv.x); b = __half22float2(*(__half2*)&gzv.y);
        gz[0] = a.x; gz[1] = a.y; gz[2] = b.x; gz[3] = b.y;
        a = __half22float2(*(__half2*)&giv.x); b = __half22float2(*(__half2*)&giv.y);
        gi[0] = a.x; gi[1] = a.y; gi[2] = b.x; gi[3] = b.y;
        a = __half22float2(*(__half2*)&ghv.x); b = __half22float2(*(__half2*)&ghv.y);
        gh[0] = a.x; gh[1] = a.y; gh[2] = b.x; gh[3] = b.y;
    }
    float4 b1r = *(const float4*)&bih[j],       b2r = *(const float4*)&bhh[j];
    float4 b1z = *(const float4*)&bih[128 + j], b2z = *(const float4*)&bhh[128 + j];
    float4 b1n = *(const float4*)&bih[256 + j], b2n = *(const float4*)&bhh[256 + j];
    float4 hv  = *(const float4*)&mem[(size_t)g_hidx[row] * D + j];
    const float* b1rp = &b1r.x; const float* b2rp = &b2r.x;
    const float* b1zp = &b1z.x; const float* b2zp = &b2z.x;
    const float* b1np = &b1n.x; const float* b2np = &b2n.x;
    const float* hp = &hv.x;
    float o[4];
    #pragma unroll
    for (int q = 0; q < 4; ++q) {
        float r = 1.f / (1.f + expf(-(gr[q] + b1rp[q] + b2rp[q])));
        float z = 1.f / (1.f + expf(-(gz[q] + b1zp[q] + b2zp[q])));
        float n = tanhf(gi[q] + b1np[q] + r * (gh[q] + b2np[q]));
        o[q] = (1.f - z) * n + z * hp[q];
    }
    *(float4*)&out[((size_t)br * NROWS + row) * D + j] = make_float4(o[0], o[1], o[2], o[3]);
}

// ---------------- launch ----------------
extern "C" void kernel_launch(void* const* d_in, const int* in_sizes, int n_in,
                              void* d_out, int out_size)
{
    const int*   n_id        = (const int*)  d_in[0];
    const float* memory      = (const float*)d_in[1];
    const float* pos_mem     = (const float*)d_in[2];
    const float* pos_emb     = (const float*)d_in[3];
    const float* raw_msg_s   = (const float*)d_in[4];
    const float* raw_msg_d   = (const float*)d_in[5];
    const int*   other_s     = (const int*)  d_in[6];
    const int*   other_d     = (const int*)  d_in[7];
    const int*   t_s         = (const int*)  d_in[8];
    const int*   t_d         = (const int*)  d_in[9];
    const int*   last_update = (const int*)  d_in[10];
    const float* w_time_mem  = (const float*)d_in[11];
    const float* b_time_mem  = (const float*)d_in[12];
    const float* w_time_pos  = (const float*)d_in[13];
    const float* b_time_pos  = (const float*)d_in[14];
    const float* Wih_mem     = (const float*)d_in[15];
    const float* Whh_mem     = (const float*)d_in[16];
    const float* bih_mem     = (const float*)d_in[17];
    const float* bhh_mem     = (const float*)d_in[18];
    const float* Wih_pos     = (const float*)d_in[19];
    const float* Whh_pos     = (const float*)d_in[20];
    const float* bih_pos     = (const float*)d_in[21];
    const float* bhh_pos     = (const float*)d_in[22];
    float* out = (float*)d_out;

    cudaFuncSetAttribute(gemm16_kernel, cudaFuncAttributeMaxDynamicSharedMemorySize, SMEM_SZ);

    te_table16_kernel<<<TMAX, 128>>>(w_time_mem, b_time_mem, w_time_pos, b_time_pos);
    wround16_kernel<<<dim3(768, 4), 256>>>(Wih_mem, Wih_pos, Whh_mem, Whh_pos);
    conv_mem_kernel<<<dim3(NROWS * D / (256 * 4), 2), 256>>>(memory, pos_mem);
    prep_kernel<<<NROWS / 256, 256>>>(n_id, other_s, other_d, t_s, t_d, last_update, out);
    feat_kernel<<<NROWS / 4, 256>>>(raw_msg_s, raw_msg_d, pos_emb);

    gemm16_kernel<<<dim3(NROWS / 128, 4, 2), 128, SMEM_SZ>>>();

    gru_kernel<<<dim3(NROWS / 8, 2), 256>>>(memory, pos_mem, bih_mem, bhh_mem, bih_pos, bhh_pos, out);
}

// round 12
// speedup vs baseline: 1.0057x; 1.0057x over previous
#include <cuda_runtime.h>
#include <cuda_fp16.h>
#include <cstdint>

#define NROWS 65536
#define D 128
#define TMAX 2048

// smem: rp 4KB | 3 stages x (A 16KB + W 16KB)
#define A_OFF   4096
#define STAGE   32768
#define SMEM_SZ (4096 + 3 * 32768)

// ---------------- scratch ----------------
__device__ __half g_G16[(size_t)2 * NROWS * 512];   // per row: [r_sum | z_sum | inn | hn]
__device__ __half g_mem16[2][(size_t)NROWS * D];
__device__ __half g_feat16[2][(size_t)NROWS * D];
__device__ __half g_TEtab16[2 * TMAX * D];
__device__ __half g_Wih16[2][384 * 512];
__device__ __half g_Whh16[2][384 * 128];
__device__ int g_hidx[NROWS], g_gidx[NROWS], g_trel[NROWS], g_fidx1[NROWS], g_pick[NROWS];

// ---------------- ptx helpers ----------------
__device__ __forceinline__ void mma_f16(float* c, const uint32_t* a, uint32_t b0, uint32_t b1) {
    asm volatile(
        "mma.sync.aligned.m16n8k16.row.col.f32.f16.f16.f32 "
        "{%0,%1,%2,%3}, {%4,%5,%6,%7}, {%8,%9}, {%0,%1,%2,%3};\n"
        : "+f"(c[0]), "+f"(c[1]), "+f"(c[2]), "+f"(c[3])
        : "r"(a[0]), "r"(a[1]), "r"(a[2]), "r"(a[3]), "r"(b0), "r"(b1));
}
__device__ __forceinline__ void cp16(uint32_t dst, const void* src) {
    asm volatile("cp.async.cg.shared.global [%0], [%1], 16;\n" :: "r"(dst), "l"(src));
}
__device__ __forceinline__ void ldsm4(uint32_t* r, uint32_t addr) {
    asm volatile("ldmatrix.sync.aligned.m8n8.x4.shared.b16 {%0,%1,%2,%3}, [%4];"
                 : "=r"(r[0]), "=r"(r[1]), "=r"(r[2]), "=r"(r[3]) : "r"(addr));
}

// ---------------- one-time conversion kernels ----------------
__global__ void te_table16_kernel(const float* __restrict__ wm, const float* __restrict__ bm,
                                  const float* __restrict__ wp, const float* __restrict__ bp)
{
    int t = blockIdx.x, k = threadIdx.x;
    float tf = (float)t;
    g_TEtab16[t * D + k]            = __float2half_rn(cosf(tf * wm[k] + bm[k]));
    g_TEtab16[TMAX * D + t * D + k] = __float2half_rn(cosf(tf * wp[k] + bp[k]));
}

__global__ void wround16_kernel(const float* __restrict__ Wih0, const float* __restrict__ Wih1,
                                const float* __restrict__ Whh0, const float* __restrict__ Whh1)
{
    int which = blockIdx.y;
    int n = (which < 2) ? 384 * 512 : 384 * 128;
    int i = blockIdx.x * 256 + threadIdx.x;
    if (i >= n) return;
    const float* s = (which == 0) ? Wih0 : (which == 1) ? Wih1 : (which == 2) ? Whh0 : Whh1;
    __half* d      = (which == 0) ? g_Wih16[0] : (which == 1) ? g_Wih16[1]
                   : (which == 2) ? g_Whh16[0] : g_Whh16[1];
    d[i] = __float2half_rn(s[i]);
}

__global__ void conv_mem_kernel(const float* __restrict__ m0, const float* __restrict__ m1)
{
    int arr = blockIdx.y;
    const float* s = arr ? m1 : m0;
    __half* d = g_mem16[arr];
    size_t i = ((size_t)blockIdx.x * 256 + threadIdx.x) * 4;
    float4 v = *(const float4*)(s + i);
    *(__half2*)(d + i)     = __floats2half2_rn(v.x, v.y);
    *(__half2*)(d + i + 2) = __floats2half2_rn(v.z, v.w);
}

// ---------------- descriptors + last_up ----------------
__global__ void prep_kernel(const int* __restrict__ n_id,
                            const int* __restrict__ other_s, const int* __restrict__ other_d,
                            const int* __restrict__ t_s, const int* __restrict__ t_d,
                            const int* __restrict__ last_update,
                            float* __restrict__ out)
{
    int row = blockIdx.x * 256 + threadIdx.x;
    if (row >= NROWS) return;
    int ts = t_s[row], td = t_d[row];
    bool pick = (ts >= td);
    int nid = n_id[row];
    int tpick = pick ? ts : td;
    g_hidx[row]  = nid;
    g_gidx[row]  = pick ? other_s[row] : other_d[row];
    g_trel[row]  = tpick - last_update[nid];
    g_pick[row]  = pick ? 1 : 0;
    g_fidx1[row] = pick ? nid : other_d[row];
    out[(size_t)2 * NROWS * D + row] = (float)tpick;
}

// ---------------- feature pick/gather + convert ----------------
__global__ void feat_kernel(const float* __restrict__ msg_s, const float* __restrict__ msg_d,
                            const float* __restrict__ pos_emb)
{
    int warp = threadIdx.x >> 5, lane = threadIdx.x & 31;
    int row = blockIdx.x * 4 + (warp >> 1);
    int br  = warp & 1;
    const float* src = br ? pos_emb + (size_t)g_fidx1[row] * D
                          : (g_pick[row] ? msg_s : msg_d) + (size_t)row * D;
    float4 v = *(const float4*)(src + lane * 4);
    __half* d = g_feat16[br] + (size_t)row * D + lane * 4;
    *(__half2*)d       = __floats2half2_rn(v.x, v.y);
    *(__half2*)(d + 2) = __floats2half2_rn(v.z, v.w);
}

// ---------------- pipelined FP16 GEMM, 256 threads, warp grid 2m x 4n, tile m64n32, BK=64 ----------------
// grid (512 row-blocks, 4 gate-blocks, 2 branches); BM=128, BN=128.
// gates: nb0=r_sum (10 slabs: 8 Wih + 2 Whh), nb1=z_sum (10), nb2=inn (8), nb3=hn (2)
__global__ void __launch_bounds__(256, 2)
gemm16_kernel()
{
    extern __shared__ char sm[];
    const __half** rp = (const __half**)sm;
    uint32_t su = (uint32_t)__cvta_generic_to_shared(sm);

    int br = blockIdx.z, nb = blockIdx.y, rb = blockIdx.x;
    int NSslab = (nb == 3) ? 2 : ((nb == 2) ? 8 : 10);
    int whh_base = (nb < 2) ? nb * 128 : 256;

    const __half* WihB = g_Wih16[br];
    const __half* WhhB = g_Whh16[br];

    int tid = threadIdx.x, lane = tid & 31, warp = tid >> 5;
    int wm = warp & 1, wn = warp >> 1;

    if (tid < 128) {
        int R = rb * 128 + tid;
        rp[tid]       = g_mem16[br] + (size_t)g_hidx[R] * D;
        rp[128 + tid] = g_mem16[br] + (size_t)g_gidx[R] * D;
        rp[256 + tid] = g_feat16[br] + (size_t)R * D;
        rp[384 + tid] = g_TEtab16 + (size_t)br * TMAX * D + (size_t)g_trel[R] * D;
    }
    __syncthreads();

    // loader: threads 0-127 load A row tid; threads 128-255 load W row (tid-128); 8 granules each
    int lrow = tid & 127;
    int lx7  = lrow & 7;
    bool isA = (tid < 128);

    auto issue = [&](int s) {
        if (s < NSslab) {
            uint32_t base = su + A_OFF + (s % 3) * STAGE;
            bool is_wih = (nb <= 2) && (s < 8);
            int koffA = is_wih ? (s & 1) * 128 : ((nb < 2) ? (s - 8) : s) * 128;  // bytes
            const char* src;
            uint32_t dst;
            if (isA) {
                int c = is_wih ? (s >> 1) : 0;
                src = (const char*)rp[c * 128 + lrow] + koffA;
                dst = base + lrow * 128;
            } else {
                if (is_wih) src = (const char*)(WihB + (size_t)(nb * 128 + lrow) * 512) + s * 128;
                else        src = (const char*)(WhhB + (size_t)(whh_base + lrow) * 128) + koffA;
                dst = base + 16384 + lrow * 128;
            }
            #pragma unroll
            for (int j = 0; j < 8; ++j) {
                uint32_t sw = (uint32_t)((j ^ lx7) << 4);
                cp16(dst + sw, src + j * 16);
            }
        }
        asm volatile("cp.async.commit_group;\n");
    };

    // fragment lane constants
    int x7 = lane & 7;
    int a_kh = lane >> 4;
    int b_kh = (lane >> 3) & 1;
    uint32_t aRowOff = (uint32_t)((wm * 64 + ((lane >> 3) & 1) * 8 + (lane & 7)) * 128);
    uint32_t bRowOff = (uint32_t)((wn * 32 + (lane >> 4) * 8 + (lane & 7)) * 128);

    float acc[4][4][4];
    #pragma unroll
    for (int i = 0; i < 4; ++i)
        #pragma unroll
        for (int n = 0; n < 4; ++n)
            #pragma unroll
            for (int q = 0; q < 4; ++q) acc[i][n][q] = 0.f;

    issue(0);
    issue(1);

    for (int s = 0; s < NSslab; ++s) {
        asm volatile("cp.async.wait_group 1;\n");
        __syncthreads();
        issue(s + 2);

        uint32_t aSt = su + A_OFF + (s % 3) * STAGE;
        uint32_t wSt = aSt + 16384;
        #pragma unroll
        for (int s2 = 0; s2 < 4; ++s2) {
            uint32_t aj = (uint32_t)(((s2 * 2 + a_kh) ^ x7) << 4);
            uint32_t bj = (uint32_t)(((s2 * 2 + b_kh) ^ x7) << 4);
            uint32_t Af[4][4];
            #pragma unroll
            for (int mf = 0; mf < 4; ++mf)
                ldsm4(Af[mf], aSt + aRowOff + mf * 2048 + aj);
            uint32_t Bf[2][4];
            #pragma unroll
            for (int p = 0; p < 2; ++p)
                ldsm4(Bf[p], wSt + bRowOff + p * 2048 + bj);
            #pragma unroll
            for (int nf = 0; nf < 4; ++nf) {
                uint32_t b0 = Bf[nf >> 1][(nf & 1) * 2];
                uint32_t b1 = Bf[nf >> 1][(nf & 1) * 2 + 1];
                #pragma unroll
                for (int mf = 0; mf < 4; ++mf)
                    mma_f16(&acc[mf][nf][0], Af[mf], b0, b1);
            }
        }
    }

    // store to G16
    size_t gb = (size_t)br * NROWS * 512;
    #pragma unroll
    for (int mf = 0; mf < 4; ++mf) {
        int r = rb * 128 + wm * 64 + mf * 16 + (lane >> 2);
        #pragma unroll
        for (int nf = 0; nf < 4; ++nf) {
            int col = nb * 128 + wn * 32 + nf * 8 + (lane & 3) * 2;
            *(__half2*)&g_G16[gb + (size_t)r * 512 + col]       = __floats2half2_rn(acc[mf][nf][0], acc[mf][nf][1]);
            *(__half2*)&g_G16[gb + (size_t)(r + 8) * 512 + col] = __floats2half2_rn(acc[mf][nf][2], acc[mf][nf][3]);
        }
    }
}

// ---------------- GRU epilogue: warp per row, fp16 G ----------------
__global__ void gru_kernel(const float* __restrict__ memory, const float* __restrict__ pos_mem,
                           const float* __restrict__ bih0, const float* __restrict__ bhh0,
                           const float* __restrict__ bih1, const float* __restrict__ bhh1,
                           float* __restrict__ out)
{
    int warp = threadIdx.x >> 5, lane = threadIdx.x & 31;
    int row = blockIdx.x * 8 + warp;
    int br  = blockIdx.y;
    int j   = lane * 4;
    const __half* G  = g_G16 + ((size_t)br * NROWS + row) * 512;
    const float* bih = br ? bih1 : bih0;
    const float* bhh = br ? bhh1 : bhh0;
    const float* mem = br ? pos_mem : memory;

    uint2 grv = *(const uint2*)&G[j];
    uint2 gzv = *(const uint2*)&G[128 + j];
    uint2 giv = *(const uint2*)&G[256 + j];
    uint2 ghv = *(const uint2*)&G[384 + j];
    float gr[4], gz[4], gi[4], gh[4];
    {
        float2 a = __half22float2(*(__half2*)&grv.x), b = __half22float2(*(__half2*)&grv.y);
        gr[0] = a.x; gr[1] = a.y; gr[2] = b.x; gr[3] = b.y;
        a = __half22float2(*(__half2*)&gzv.x); b = __half22float2(*(__half2*)&gzv.y);
        gz[0] = a.x; gz[1] = a.y; gz[2] = b.x; gz[3] = b.y;
        a = __half22float2(*(__half2*)&giv.x); b = __half22float2(*(__half2*)&giv.y);
        gi[0] = a.x; gi[1] = a.y; gi[2] = b.x; gi[3] = b.y;
        a = __half22float2(*(__half2*)&ghv.x); b = __half22float2(*(__half2*)&ghv.y);
        gh[0] = a.x; gh[1] = a.y; gh[2] = b.x; gh[3] = b.y;
    }
    float4 b1r = *(const float4*)&bih[j],       b2r = *(const float4*)&bhh[j];
    float4 b1z = *(const float4*)&bih[128 + j], b2z = *(const float4*)&bhh[128 + j];
    float4 b1n = *(const float4*)&bih[256 + j], b2n = *(const float4*)&bhh[256 + j];
    float4 hv  = *(const float4*)&mem[(size_t)g_hidx[row] * D + j];
    const float* b1rp = &b1r.x; const float* b2rp = &b2r.x;
    const float* b1zp = &b1z.x; const float* b2zp = &b2z.x;
    const float* b1np = &b1n.x; const float* b2np = &b2n.x;
    const float* hp = &hv.x;
    float o[4];
    #pragma unroll
    for (int q = 0; q < 4; ++q) {
        float r = 1.f / (1.f + expf(-(gr[q] + b1rp[q] + b2rp[q])));
        float z = 1.f / (1.f + expf(-(gz[q] + b1zp[q] + b2zp[q])));
        float n = tanhf(gi[q] + b1np[q] + r * (gh[q] + b2np[q]));
        o[q] = (1.f - z) * n + z * hp[q];
    }
    *(float4*)&out[((size_t)br * NROWS + row) * D + j] = make_float4(o[0], o[1], o[2], o[3]);
}

// ---------------- launch ----------------
extern "C" void kernel_launch(void* const* d_in, const int* in_sizes, int n_in,
                              void* d_out, int out_size)
{
    const int*   n_id        = (const int*)  d_in[0];
    const float* memory      = (const float*)d_in[1];
    const float* pos_mem     = (const float*)d_in[2];
    const float* pos_emb     = (const float*)d_in[3];
    const float* raw_msg_s   = (const float*)d_in[4];
    const float* raw_msg_d   = (const float*)d_in[5];
    const int*   other_s     = (const int*)  d_in[6];
    const int*   other_d     = (const int*)  d_in[7];
    const int*   t_s         = (const int*)  d_in[8];
    const int*   t_d         = (const int*)  d_in[9];
    const int*   last_update = (const int*)  d_in[10];
    const float* w_time_mem  = (const float*)d_in[11];
    const float* b_time_mem  = (const float*)d_in[12];
    const float* w_time_pos  = (const float*)d_in[13];
    const float* b_time_pos  = (const float*)d_in[14];
    const float* Wih_mem     = (const float*)d_in[15];
    const float* Whh_mem     = (const float*)d_in[16];
    const float* bih_mem     = (const float*)d_in[17];
    const float* bhh_mem     = (const float*)d_in[18];
    const float* Wih_pos     = (const float*)d_in[19];
    const float* Whh_pos     = (const float*)d_in[20];
    const float* bih_pos     = (const float*)d_in[21];
    const float* bhh_pos     = (const float*)d_in[22];
    float* out = (float*)d_out;

    cudaFuncSetAttribute(gemm16_kernel, cudaFuncAttributeMaxDynamicSharedMemorySize, SMEM_SZ);

    te_table16_kernel<<<TMAX, 128>>>(w_time_mem, b_time_mem, w_time_pos, b_time_pos);
    wround16_kernel<<<dim3(768, 4), 256>>>(Wih_mem, Wih_pos, Whh_mem, Whh_pos);
    conv_mem_kernel<<<dim3(NROWS * D / (256 * 4), 2), 256>>>(memory, pos_mem);
    prep_kernel<<<NROWS / 256, 256>>>(n_id, other_s, other_d, t_s, t_d, last_update, out);
    feat_kernel<<<NROWS / 4, 256>>>(raw_msg_s, raw_msg_d, pos_emb);

    gemm16_kernel<<<dim3(NROWS / 128, 4, 2), 256, SMEM_SZ>>>();

    gru_kernel<<<dim3(NROWS / 8, 2), 256>>>(memory, pos_mem, bih_mem, bhh_mem, bih_pos, bhh_pos, out);
}

// round 13
// speedup vs baseline: 1.4152x; 1.4072x over previous
#include <cuda_runtime.h>
#include <cuda_fp16.h>
#include <cstdint>

#define NROWS 65536
#define D 128
#define TMAX 2048

// smem: rp 4KB | 3 stages x (A 16KB + W 16KB)
#define A_OFF   4096
#define STAGE   32768
#define SMEM_SZ (4096 + 3 * 32768)

// ---------------- scratch ----------------
__device__ __half g_G16[(size_t)2 * NROWS * 512];   // per row: [r_sum | z_sum | inn | hn]
__device__ __half g_mem16[2][(size_t)NROWS * D];
__device__ __half g_feat16[2][(size_t)NROWS * D];
__device__ __half g_TEtab16[2 * TMAX * D];
__device__ __half g_Wih16[2][384 * 512];
__device__ __half g_Whh16[2][384 * 128];
__device__ int g_hidx[NROWS], g_gidx[NROWS], g_trel[NROWS], g_fidx1[NROWS], g_pick[NROWS];

// ---------------- ptx helpers ----------------
__device__ __forceinline__ void mma_f16(float* c, const uint32_t* a, uint32_t b0, uint32_t b1) {
    asm volatile(
        "mma.sync.aligned.m16n8k16.row.col.f32.f16.f16.f32 "
        "{%0,%1,%2,%3}, {%4,%5,%6,%7}, {%8,%9}, {%0,%1,%2,%3};\n"
        : "+f"(c[0]), "+f"(c[1]), "+f"(c[2]), "+f"(c[3])
        : "r"(a[0]), "r"(a[1]), "r"(a[2]), "r"(a[3]), "r"(b0), "r"(b1));
}
__device__ __forceinline__ void cp16(uint32_t dst, const void* src) {
    asm volatile("cp.async.cg.shared.global [%0], [%1], 16;\n" :: "r"(dst), "l"(src));
}
__device__ __forceinline__ void ldsm4(uint32_t* r, uint32_t addr) {
    asm volatile("ldmatrix.sync.aligned.m8n8.x4.shared.b16 {%0,%1,%2,%3}, [%4];"
                 : "=r"(r[0]), "=r"(r[1]), "=r"(r[2]), "=r"(r[3]) : "r"(addr));
}

// ---------------- one-time conversion kernels ----------------
__global__ void te_table16_kernel(const float* __restrict__ wm, const float* __restrict__ bm,
                                  const float* __restrict__ wp, const float* __restrict__ bp)
{
    int t = blockIdx.x, k = threadIdx.x;
    float tf = (float)t;
    g_TEtab16[t * D + k]            = __float2half_rn(cosf(tf * wm[k] + bm[k]));
    g_TEtab16[TMAX * D + t * D + k] = __float2half_rn(cosf(tf * wp[k] + bp[k]));
}

__global__ void wround16_kernel(const float* __restrict__ Wih0, const float* __restrict__ Wih1,
                                const float* __restrict__ Whh0, const float* __restrict__ Whh1)
{
    int which = blockIdx.y;
    int n = (which < 2) ? 384 * 512 : 384 * 128;
    int i = blockIdx.x * 256 + threadIdx.x;
    if (i >= n) return;
    const float* s = (which == 0) ? Wih0 : (which == 1) ? Wih1 : (which == 2) ? Whh0 : Whh1;
    __half* d      = (which == 0) ? g_Wih16[0] : (which == 1) ? g_Wih16[1]
                   : (which == 2) ? g_Whh16[0] : g_Whh16[1];
    d[i] = __float2half_rn(s[i]);
}

__global__ void conv_mem_kernel(const float* __restrict__ m0, const float* __restrict__ m1)
{
    int arr = blockIdx.y;
    const float* s = arr ? m1 : m0;
    __half* d = g_mem16[arr];
    size_t i = ((size_t)blockIdx.x * 256 + threadIdx.x) * 4;
    float4 v = *(const float4*)(s + i);
    *(__half2*)(d + i)     = __floats2half2_rn(v.x, v.y);
    *(__half2*)(d + i + 2) = __floats2half2_rn(v.z, v.w);
}

// ---------------- descriptors + last_up ----------------
__global__ void prep_kernel(const int* __restrict__ n_id,
                            const int* __restrict__ other_s, const int* __restrict__ other_d,
                            const int* __restrict__ t_s, const int* __restrict__ t_d,
                            const int* __restrict__ last_update,
                            float* __restrict__ out)
{
    int row = blockIdx.x * 256 + threadIdx.x;
    if (row >= NROWS) return;
    int ts = t_s[row], td = t_d[row];
    bool pick = (ts >= td);
    int nid = n_id[row];
    int tpick = pick ? ts : td;
    g_hidx[row]  = nid;
    g_gidx[row]  = pick ? other_s[row] : other_d[row];
    g_trel[row]  = tpick - last_update[nid];
    g_pick[row]  = pick ? 1 : 0;
    g_fidx1[row] = pick ? nid : other_d[row];
    out[(size_t)2 * NROWS * D + row] = (float)tpick;
}

// ---------------- feature pick/gather + convert ----------------
__global__ void feat_kernel(const float* __restrict__ msg_s, const float* __restrict__ msg_d,
                            const float* __restrict__ pos_emb)
{
    int warp = threadIdx.x >> 5, lane = threadIdx.x & 31;
    int row = blockIdx.x * 4 + (warp >> 1);
    int br  = warp & 1;
    const float* src = br ? pos_emb + (size_t)g_fidx1[row] * D
                          : (g_pick[row] ? msg_s : msg_d) + (size_t)row * D;
    float4 v = *(const float4*)(src + lane * 4);
    __half* d = g_feat16[br] + (size_t)row * D + lane * 4;
    *(__half2*)d       = __floats2half2_rn(v.x, v.y);
    *(__half2*)(d + 2) = __floats2half2_rn(v.z, v.w);
}

// ---------------- pipelined FP16 GEMM, 512 threads, 4x4 warp grid m32n32, BK=64 ----------------
// grid (512 row-blocks, 4 gate-blocks, 2 branches); BM=128, BN=128.
// gates: nb0=r_sum (10 slabs: 8 Wih + 2 Whh), nb1=z_sum (10), nb2=inn (8), nb3=hn (2)
__global__ void __launch_bounds__(512, 2)
gemm16_kernel()
{
    extern __shared__ char sm[];
    const __half** rp = (const __half**)sm;
    uint32_t su = (uint32_t)__cvta_generic_to_shared(sm);

    int br = blockIdx.z, nb = blockIdx.y, rb = blockIdx.x;
    int NSslab = (nb == 3) ? 2 : ((nb == 2) ? 8 : 10);
    int whh_base = (nb < 2) ? nb * 128 : 256;

    const __half* WihB = g_Wih16[br];
    const __half* WhhB = g_Whh16[br];

    int tid = threadIdx.x, lane = tid & 31, warp = tid >> 5;
    int wm = warp & 3, wn = warp >> 2;

    if (tid < 128) {
        int R = rb * 128 + tid;
        rp[tid]       = g_mem16[br] + (size_t)g_hidx[R] * D;
        rp[128 + tid] = g_mem16[br] + (size_t)g_gidx[R] * D;
        rp[256 + tid] = g_feat16[br] + (size_t)R * D;
        rp[384 + tid] = g_TEtab16 + (size_t)br * TMAX * D + (size_t)g_trel[R] * D;
    }
    __syncthreads();

    auto issue = [&](int s) {
        if (s < NSslab) {
            int st = s % 3;
            bool is_wih = (nb <= 2) && (s < 8);
            int c     = is_wih ? (s >> 1) : 0;
            int koffA = is_wih ? (s & 1) * 128 : ((nb < 2) ? (s - 8) : s) * 128;  // bytes
            uint32_t base = su + A_OFF + st * STAGE;
            #pragma unroll
            for (int p = 0; p < 2; ++p) {
                int g = tid + p * 512;
                int row = g >> 3, j = g & 7;
                int jp = ((j ^ (row & 7)) << 4);
                cp16(base + g * 16, (const char*)rp[c * 128 + row] + koffA + jp);
                const char* wsrc;
                if (is_wih) wsrc = (const char*)(WihB + (size_t)(nb * 128 + row) * 512) + s * 128 + jp;
                else        wsrc = (const char*)(WhhB + (size_t)(whh_base + row) * 128) + koffA + jp;
                cp16(base + 16384 + g * 16, wsrc);
            }
        }
        asm volatile("cp.async.commit_group;\n");
    };

    // fragment lane constants (row&7 == lane&7 for all tiles)
    int x7 = lane & 7;
    int a_kh = lane >> 4;
    int b_kh = (lane >> 3) & 1;
    uint32_t aRow = (uint32_t)((wm * 32 + ((lane >> 3) & 1) * 8 + (lane & 7)) * 128);
    uint32_t bRow = (uint32_t)((wn * 32 + (lane >> 4) * 8 + (lane & 7)) * 128);

    float acc[2][4][4];
    #pragma unroll
    for (int i = 0; i < 2; ++i)
        #pragma unroll
        for (int j = 0; j < 4; ++j)
            #pragma unroll
            for (int q = 0; q < 4; ++q) acc[i][j][q] = 0.f;

    issue(0);
    issue(1);

    for (int s = 0; s < NSslab; ++s) {
        asm volatile("cp.async.wait_group 1;\n");
        __syncthreads();
        issue(s + 2);

        uint32_t aSt = su + A_OFF + (s % 3) * STAGE;
        uint32_t wSt = aSt + 16384;
        #pragma unroll
        for (int s2 = 0; s2 < 4; ++s2) {
            uint32_t aj = (uint32_t)(((s2 * 2 + a_kh) ^ x7) << 4);
            uint32_t bj = (uint32_t)(((s2 * 2 + b_kh) ^ x7) << 4);
            uint32_t Af[2][4];
            #pragma unroll
            for (int mf = 0; mf < 2; ++mf)
                ldsm4(Af[mf], aSt + aRow + mf * 2048 + aj);
            uint32_t Bf[2][4];
            #pragma unroll
            for (int p = 0; p < 2; ++p)
                ldsm4(Bf[p], wSt + bRow + p * 2048 + bj);
            #pragma unroll
            for (int nf = 0; nf < 4; ++nf) {
                uint32_t b0 = Bf[nf >> 1][(nf & 1) * 2];
                uint32_t b1 = Bf[nf >> 1][(nf & 1) * 2 + 1];
                #pragma unroll
                for (int mf = 0; mf < 2; ++mf)
                    mma_f16(&acc[mf][nf][0], Af[mf], b0, b1);
            }
        }
    }

    // store to G16
    size_t gb = (size_t)br * NROWS * 512;
    #pragma unroll
    for (int mf = 0; mf < 2; ++mf) {
        int r = rb * 128 + wm * 32 + mf * 16 + (lane >> 2);
        #pragma unroll
        for (int nf = 0; nf < 4; ++nf) {
            int col = nb * 128 + wn * 32 + nf * 8 + (lane & 3) * 2;
            *(__half2*)&g_G16[gb + (size_t)r * 512 + col]       = __floats2half2_rn(acc[mf][nf][0], acc[mf][nf][1]);
            *(__half2*)&g_G16[gb + (size_t)(r + 8) * 512 + col] = __floats2half2_rn(acc[mf][nf][2], acc[mf][nf][3]);
        }
    }
}

// ---------------- GRU epilogue: warp per row, fp16 G ----------------
__global__ void gru_kernel(const float* __restrict__ memory, const float* __restrict__ pos_mem,
                           const float* __restrict__ bih0, const float* __restrict__ bhh0,
                           const float* __restrict__ bih1, const float* __restrict__ bhh1,
                           float* __restrict__ out)
{
    int warp = threadIdx.x >> 5, lane = threadIdx.x & 31;
    int row = blockIdx.x * 8 + warp;
    int br  = blockIdx.y;
    int j   = lane * 4;
    const __half* G  = g_G16 + ((size_t)br * NROWS + row) * 512;
    const float* bih = br ? bih1 : bih0;
    const float* bhh = br ? bhh1 : bhh0;
    const float* mem = br ? pos_mem : memory;

    uint2 grv = *(const uint2*)&G[j];
    uint2 gzv = *(const uint2*)&G[128 + j];
    uint2 giv = *(const uint2*)&G[256 + j];
    uint2 ghv = *(const uint2*)&G[384 + j];
    float gr[4], gz[4], gi[4], gh[4];
    {
        float2 a = __half22float2(*(__half2*)&grv.x), b = __half22float2(*(__half2*)&grv.y);
        gr[0] = a.x; gr[1] = a.y; gr[2] = b.x; gr[3] = b.y;
        a = __half22float2(*(__half2*)&gzv.x); b = __half22float2(*(__half2*)&gzv.y);
        gz[0] = a.x; gz[1] = a.y; gz[2] = b.x; gz[3] = b.y;
        a = __half22float2(*(__half2*)&giv.x); b = __half22float2(*(__half2*)&giv.y);
        gi[0] = a.x; gi[1] = a.y; gi[2] = b.x; gi[3] = b.y;
        a = __half22float2(*(__half2*)&ghv.x); b = __half22float2(*(__half2*)&ghv.y);
        gh[0] = a.x; gh[1] = a.y; gh[2] = b.x; gh[3] = b.y;
    }
    float4 b1r = *(const float4*)&bih[j],       b2r = *(const float4*)&bhh[j];
    float4 b1z = *(const float4*)&bih[128 + j], b2z = *(const float4*)&bhh[128 + j];
    float4 b1n = *(const float4*)&bih[256 + j], b2n = *(const float4*)&bhh[256 + j];
    float4 hv  = *(const float4*)&mem[(size_t)g_hidx[row] * D + j];
    const float* b1rp = &b1r.x; const float* b2rp = &b2r.x;
    const float* b1zp = &b1z.x; const float* b2zp = &b2z.x;
    const float* b1np = &b1n.x; const float* b2np = &b2n.x;
    const float* hp = &hv.x;
    float o[4];
    #pragma unroll
    for (int q = 0; q < 4; ++q) {
        float r = 1.f / (1.f + expf(-(gr[q] + b1rp[q] + b2rp[q])));
        float z = 1.f / (1.f + expf(-(gz[q] + b1zp[q] + b2zp[q])));
        float n = tanhf(gi[q] + b1np[q] + r * (gh[q] + b2np[q]));
        o[q] = (1.f - z) * n + z * hp[q];
    }
    *(float4*)&out[((size_t)br * NROWS + row) * D + j] = make_float4(o[0], o[1], o[2], o[3]);
}

// ---------------- launch ----------------
extern "C" void kernel_launch(void* const* d_in, const int* in_sizes, int n_in,
                              void* d_out, int out_size)
{
    const int*   n_id        = (const int*)  d_in[0];
    const float* memory      = (const float*)d_in[1];
    const float* pos_mem     = (const float*)d_in[2];
    const float* pos_emb     = (const float*)d_in[3];
    const float* raw_msg_s   = (const float*)d_in[4];
    const float* raw_msg_d   = (const float*)d_in[5];
    const int*   other_s     = (const int*)  d_in[6];
    const int*   other_d     = (const int*)  d_in[7];
    const int*   t_s         = (const int*)  d_in[8];
    const int*   t_d         = (const int*)  d_in[9];
    const int*   last_update = (const int*)  d_in[10];
    const float* w_time_mem  = (const float*)d_in[11];
    const float* b_time_mem  = (const float*)d_in[12];
    const float* w_time_pos  = (const float*)d_in[13];
    const float* b_time_pos  = (const float*)d_in[14];
    const float* Wih_mem     = (const float*)d_in[15];
    const float* Whh_mem     = (const float*)d_in[16];
    const float* bih_mem     = (const float*)d_in[17];
    const float* bhh_mem     = (const float*)d_in[18];
    const float* Wih_pos     = (const float*)d_in[19];
    const float* Whh_pos     = (const float*)d_in[20];
    const float* bih_pos     = (const float*)d_in[21];
    const float* bhh_pos     = (const float*)d_in[22];
    float* out = (float*)d_out;

    cudaFuncSetAttribute(gemm16_kernel, cudaFuncAttributeMaxDynamicSharedMemorySize, SMEM_SZ);

    te_table16_kernel<<<TMAX, 128>>>(w_time_mem, b_time_mem, w_time_pos, b_time_pos);
    wround16_kernel<<<dim3(768, 4), 256>>>(Wih_mem, Wih_pos, Whh_mem, Whh_pos);
    conv_mem_kernel<<<dim3(NROWS * D / (256 * 4), 2), 256>>>(memory, pos_mem);
    prep_kernel<<<NROWS / 256, 256>>>(n_id, other_s, other_d, t_s, t_d, last_update, out);
    feat_kernel<<<NROWS / 4, 256>>>(raw_msg_s, raw_msg_d, pos_emb);

    gemm16_kernel<<<dim3(NROWS / 128, 4, 2), 512, SMEM_SZ>>>();

    gru_kernel<<<dim3(NROWS / 8, 2), 256>>>(memory, pos_mem, bih_mem, bhh_mem, bih_pos, bhh_pos, out);
}